// round 16
// baseline (speedup 1.0000x reference)
#include <cuda_runtime.h>
#include <cstdint>

// VectorQuantizer: B=32, T=4096, D=64, K=512, N = 131072 tokens
// out layout (float32): [ z_q_st : N*64 ][ indices(as float) : N ][ loss : 1 ]

#define NTOK   131072
#define FIXCAP 8192
#define MU     6e-5f    // s-space (s = -2*dot) gap threshold, R2-proven

__device__ int    g_idx[NTOK];
__device__ int    g_fixlist[FIXCAP];
__device__ int    g_fixcount;
__device__ float  g_wsq[512];
__device__ double g_loss;

#define FFMA2(acc, a, b) \
    asm("fma.rn.f32x2 %0, %1, %2, %0;" : "+l"(acc) : "l"(a), "l"(b))

__device__ __forceinline__ float2 u2f(unsigned long long v) {
    float2 f;
    asm("mov.b64 {%0, %1}, %2;" : "=f"(f.x), "=f"(f.y) : "l"(v));
    return f;
}

__device__ __forceinline__ uint32_t smem_u32(const void* p) {
    uint32_t a;
    asm("{ .reg .u64 t; cvta.to.shared.u64 t, %1; cvt.u32.u64 %0, t; }"
        : "=r"(a) : "l"(p));
    return a;
}

// ---------------------------------------------------------------------------
// Prep: wsq[k] via XLA-style warp-tree fp32 reduce; zero accumulators.
// ---------------------------------------------------------------------------
__global__ void vq_prep(const float* __restrict__ W) {
    int tid = threadIdx.x;
    int k   = blockIdx.x * 8 + (tid >> 5);
    int l   = tid & 31;
    if (blockIdx.x == 0 && tid == 0) { g_loss = 0.0; g_fixcount = 0; }
    float w0 = W[k * 64 + l];
    float w1 = W[k * 64 + l + 32];
    float v  = __fadd_rn(__fmul_rn(w0, w0), __fmul_rn(w1, w1));
    #pragma unroll
    for (int off = 16; off >= 1; off >>= 1)
        v = __fadd_rn(v, __shfl_down_sync(0xffffffffu, v, off));
    if (l == 0) g_wsq[k] = v;
}

// ---------------------------------------------------------------------------
// Screener v5: token-per-thread + cp.async double-buffered W tiles.
// 256 thr/block, 1 token/thread; z row in regs (32 u64). W streamed as 8
// tiles of 64 codewords (16KB fp32 each, linear layout). All W reads are
// lane-uniform LDS.128 broadcasts; 4 independent f32x2 accumulator chains.
// k ascending + strict < keeps reference first-min semantics; gap<MU flags
// tokens for the bit-exact fix pass.
// ---------------------------------------------------------------------------
__global__ __launch_bounds__(256, 2) void vq_main(const float* __restrict__ z,
                                                  const float* __restrict__ W) {
    __shared__ float wbuf[2][64 * 64];   // 2 x 16KB

    const int tid   = threadIdx.x;
    const int token = blockIdx.x * 256 + tid;

    // own token row -> registers (64 floats = 32 u64 pairs)
    unsigned long long zr[32];
    {
        const ulonglong2* zg = (const ulonglong2*)(z + (size_t)token * 64);
        #pragma unroll
        for (int i = 0; i < 16; i++) {
            ulonglong2 v = zg[i];
            zr[2 * i]     = v.x;
            zr[2 * i + 1] = v.y;
        }
    }

    const float4* wg4 = (const float4*)W;          // 8192 float4 total
    const uint32_t sb0 = smem_u32(&wbuf[0][0]);
    const uint32_t sb1 = smem_u32(&wbuf[1][0]);

    // prologue: tile 0 -> buf0 (1024 float4 per tile, 4 per thread)
    #pragma unroll
    for (int i = 0; i < 4; i++) {
        uint32_t d = sb0 + (uint32_t)(tid + i * 256) * 16u;
        asm volatile("cp.async.cg.shared.global [%0], [%1], 16;"
                     :: "r"(d), "l"(wg4 + tid + i * 256) : "memory");
    }
    asm volatile("cp.async.commit_group;" ::: "memory");

    float b1 = 3.4e38f, b2 = 3.4e38f;
    int   i1 = 0;

    #pragma unroll 1
    for (int t = 0; t < 8; t++) {
        asm volatile("cp.async.wait_group 0;" ::: "memory");
        __syncthreads();

        if (t < 7) {   // prefetch tile t+1 into the other buffer
            uint32_t db = (t & 1) ? sb0 : sb1;
            const float4* src = wg4 + (t + 1) * 1024;
            #pragma unroll
            for (int i = 0; i < 4; i++) {
                uint32_t d = db + (uint32_t)(tid + i * 256) * 16u;
                asm volatile("cp.async.cg.shared.global [%0], [%1], 16;"
                             :: "r"(d), "l"(src + tid + i * 256) : "memory");
            }
            asm volatile("cp.async.commit_group;" ::: "memory");
        }

        const float* wb = wbuf[t & 1];

        #pragma unroll 1
        for (int cwg = 0; cwg < 16; cwg++) {
            const ulonglong2* wr0 = (const ulonglong2*)&wb[(cwg * 4 + 0) * 64];
            const ulonglong2* wr1 = (const ulonglong2*)&wb[(cwg * 4 + 1) * 64];
            const ulonglong2* wr2 = (const ulonglong2*)&wb[(cwg * 4 + 2) * 64];
            const ulonglong2* wr3 = (const ulonglong2*)&wb[(cwg * 4 + 3) * 64];

            unsigned long long a0 = 0ull, a1 = 0ull, a2 = 0ull, a3 = 0ull;

            #pragma unroll
            for (int dc = 0; dc < 16; dc++) {
                ulonglong2 w0 = wr0[dc];
                ulonglong2 w1 = wr1[dc];
                ulonglong2 w2 = wr2[dc];
                ulonglong2 w3 = wr3[dc];
                unsigned long long zlo = zr[2 * dc];
                unsigned long long zhi = zr[2 * dc + 1];
                FFMA2(a0, zlo, w0.x);
                FFMA2(a1, zlo, w1.x);
                FFMA2(a2, zlo, w2.x);
                FFMA2(a3, zlo, w3.x);
                FFMA2(a0, zhi, w0.y);
                FFMA2(a1, zhi, w1.y);
                FFMA2(a2, zhi, w2.y);
                FFMA2(a3, zhi, w3.y);
            }

            float2 p0 = u2f(a0), p1 = u2f(a1), p2 = u2f(a2), p3 = u2f(a3);
            float s0 = -2.0f * (p0.x + p0.y);
            float s1 = -2.0f * (p1.x + p1.y);
            float s2 = -2.0f * (p2.x + p2.y);
            float s3 = -2.0f * (p3.x + p3.y);
            int k0 = t * 64 + cwg * 4;
            if (s0 < b1) { b2 = b1; b1 = s0; i1 = k0;     } else b2 = fminf(b2, s0);
            if (s1 < b1) { b2 = b1; b1 = s1; i1 = k0 + 1; } else b2 = fminf(b2, s1);
            if (s2 < b1) { b2 = b1; b1 = s2; i1 = k0 + 2; } else b2 = fminf(b2, s2);
            if (s3 < b1) { b2 = b1; b1 = s3; i1 = k0 + 3; } else b2 = fminf(b2, s3);
        }
        __syncthreads();
    }

    g_idx[token] = i1;
    if (b2 - b1 < MU) {
        int p = atomicAdd(&g_fixcount, 1);
        if (p < FIXCAP) g_fixlist[p] = token;
    }
}

// ---------------------------------------------------------------------------
// Slow fix: for flagged tokens, replicate reference fp32 arithmetic exactly.
// Updates g_idx only (epilogue materializes).                [R2-exact text]
// ---------------------------------------------------------------------------
__global__ __launch_bounds__(128) void vq_fix(const float* __restrict__ z,
                                              const float* __restrict__ W) {
    if ((int)blockIdx.x >= g_fixcount) return;
    const int token = g_fixlist[blockIdx.x];
    const int tid = threadIdx.x;

    __shared__ float zrow[64];
    __shared__ float zsq_sh;
    __shared__ float qs[128];
    __shared__ int   ks[128];

    if (tid < 64) zrow[tid] = z[(size_t)token * 64 + tid];
    __syncthreads();

    if (tid < 32) {
        float a0 = __fmul_rn(zrow[tid], zrow[tid]);
        float a1 = __fmul_rn(zrow[tid + 32], zrow[tid + 32]);
        float v  = __fadd_rn(a0, a1);
        #pragma unroll
        for (int off = 16; off >= 1; off >>= 1)
            v = __fadd_rn(v, __shfl_down_sync(0xffffffffu, v, off));
        if (tid == 0) zsq_sh = v;
    }
    __syncthreads();
    const float zsq = zsq_sh;

    float qbest = 3.4e38f;
    int   kbest = 0x7fffffff;
    #pragma unroll
    for (int r = 0; r < 4; r++) {
        int k = tid + 128 * r;
        const float* wr = &W[(size_t)k * 64];
        float acc = 0.0f;
        #pragma unroll
        for (int d = 0; d < 64; d++)
            acc = __fmaf_rn(zrow[d], wr[d], acc);
        float y  = __fmul_rn(2.0f, acc);            // fl(2*M), exact
        float t1 = __fadd_rn(zsq, g_wsq[k]);        // fl(zsq + wsq)
        float q  = __fadd_rn(t1, -y);               // fl(t1 - 2M)
        if (q < qbest || (q == qbest && k < kbest)) { qbest = q; kbest = k; }
    }

    qs[tid] = qbest; ks[tid] = kbest;
    __syncthreads();
    for (int s = 64; s >= 1; s >>= 1) {
        if (tid < s) {
            float oq = qs[tid + s]; int ok = ks[tid + s];
            if (oq < qs[tid] || (oq == qs[tid] && ok < ks[tid])) {
                qs[tid] = oq; ks[tid] = ok;
            }
        }
        __syncthreads();
    }
    if (tid == 0) g_idx[token] = ks[0];
}

// ---------------------------------------------------------------------------
// Epilogue (R8-proven): gather z_q, z_q_st = fl(z + fl(z_q - z)), indices,
// loss partial via shuffle tree + one fp64 atomic/block.
// ---------------------------------------------------------------------------
__global__ __launch_bounds__(256) void vq_epi(const float* __restrict__ z,
                                              const float* __restrict__ W,
                                              float* __restrict__ out, int N) {
    __shared__ double red[8];
    const int tid = threadIdx.x;
    const int sub = tid & 15;
    const int tyy = tid >> 4;
    const int base = blockIdx.x * 64;
    float* idxo = out + (size_t)N * 64;

    float lsum = 0.0f;
    #pragma unroll
    for (int t = 0; t < 4; t++) {
        int token = base + t * 16 + tyy;
        int kq = g_idx[token];
        float4 zv = *(const float4*)&z[(size_t)token * 64 + sub * 4];
        float4 wv = *(const float4*)&W[(size_t)kq * 64 + sub * 4];
        float4 st;
        st.x = __fadd_rn(zv.x, __fadd_rn(wv.x, -zv.x));
        st.y = __fadd_rn(zv.y, __fadd_rn(wv.y, -zv.y));
        st.z = __fadd_rn(zv.z, __fadd_rn(wv.z, -zv.z));
        st.w = __fadd_rn(zv.w, __fadd_rn(wv.w, -zv.w));
        *(float4*)&out[(size_t)token * 64 + sub * 4] = st;
        if (sub == 0) idxo[token] = (float)kq;
        float ex = __fadd_rn(zv.x, -st.x), ey = __fadd_rn(zv.y, -st.y);
        float ez = __fadd_rn(zv.z, -st.z), ew = __fadd_rn(zv.w, -st.w);
        lsum += ex * ex + ey * ey + ez * ez + ew * ew;
    }

    double d = (double)lsum;
    #pragma unroll
    for (int off = 16; off >= 1; off >>= 1)
        d += __shfl_down_sync(0xffffffffu, d, off);
    if ((tid & 31) == 0) red[tid >> 5] = d;
    __syncthreads();
    if (tid < 32) {
        double s = (tid < 8) ? red[tid] : 0.0;
        #pragma unroll
        for (int off = 4; off >= 1; off >>= 1)
            s += __shfl_down_sync(0xffffffffu, s, off);
        if (tid == 0) atomicAdd(&g_loss, s);
    }
}

__global__ void vq_fin(float* __restrict__ out, int N) {
    out[(size_t)N * 65] = (float)(0.25 * g_loss / ((double)N * 64.0));
}

extern "C" void kernel_launch(void* const* d_in, const int* in_sizes, int n_in,
                              void* d_out, int out_size) {
    const float* z = (const float*)d_in[0];
    const float* W = (const float*)d_in[1];
    float* out = (float*)d_out;
    const int N = in_sizes[0] / 64;   // 131072 tokens

    vq_prep<<<64, 256>>>(W);
    vq_main<<<N / 256, 256>>>(z, W);
    vq_fix<<<FIXCAP, 128>>>(z, W);
    vq_epi<<<N / 64, 256>>>(z, W, out, N);
    vq_fin<<<1, 1>>>(out, N);
}